// round 11
// baseline (speedup 1.0000x reference)
#include <cuda_runtime.h>
#include <math.h>
#include <stdint.h>

#define Bq 256
#define Nq 256
#define Dq 512
#define Cq 1024
#define NCHUNK 8
#define CH_ROWS (Nq / NCHUNK)   // 32 rows per fused block
#define KSPLIT 8
#define KCH (Dq / KSPLIT)       // 64

// Scratch (device globals — no allocation allowed)
__device__ float  g_txtrn[Cq];                     // 1/||txt[c]||  (4 KB)
__device__ float  g_ppart[Bq * NCHUNK * Dq];       // partial weighted sums (4 MB)
__device__ float2 g_meta[Bq * NCHUNK];             // (m, den) per partial
__device__ float  g_pooled[Bq * Dq];               // pooled normalized tokens
__device__ float  g_lpart[KSPLIT * Bq * Cq];       // partial logits (8 MB)

__device__ __forceinline__ float warp_sum1(float v) {
#pragma unroll
    for (int o = 16; o; o >>= 1) v += __shfl_xor_sync(0xffffffffu, v, o);
    return v;
}

__device__ __forceinline__ void warp_sum4(float& a, float& b, float& c, float& d) {
#pragma unroll
    for (int o = 16; o; o >>= 1) {
        a += __shfl_xor_sync(0xffffffffu, a, o);
        b += __shfl_xor_sync(0xffffffffu, b, o);
        c += __shfl_xor_sync(0xffffffffu, c, o);
        d += __shfl_xor_sync(0xffffffffu, d, o);
    }
}

__device__ __forceinline__ uint32_t f2tf32(float v) {
    uint32_t r;
    asm("cvt.rna.tf32.f32 %0, %1;" : "=r"(r) : "f"(v));
    return r;
}
__device__ __forceinline__ uint4 tf32x4(float4 v) {
    return make_uint4(f2tf32(v.x), f2tf32(v.y), f2tf32(v.z), f2tf32(v.w));
}
__device__ __forceinline__ uint4 tf32x4s(float4 v, float s) {
    return make_uint4(f2tf32(v.x * s), f2tf32(v.y * s), f2tf32(v.z * s), f2tf32(v.w * s));
}

// ---------------------------------------------------------------------------
// K1: compute reciprocal norms of text rows (no normalized copy written).
// One warp per row. grid = C/8 = 128, block = 256. Also zeroes out[0].
// ---------------------------------------------------------------------------
__global__ void k_txtnorm(const float* __restrict__ txt, float* __restrict__ out) {
    if (blockIdx.x == 0 && threadIdx.x == 0) out[0] = 0.f;
    int w = threadIdx.x >> 5, lane = threadIdx.x & 31;
    int row = blockIdx.x * 8 + w;
    const float4* src = (const float4*)(txt + (size_t)row * Dq);
    float ss = 0.f;
#pragma unroll
    for (int i = 0; i < 4; i++) {
        float4 v = src[lane + 32 * i];
        ss += v.x * v.x + v.y * v.y + v.z * v.z + v.w * v.w;
    }
    ss = warp_sum1(ss);
    if (lane == 0) g_txtrn[row] = 1.f / fmaxf(sqrtf(ss), 1e-12f);
}

// ---------------------------------------------------------------------------
// K2 (fused streaming pass): online softmax-weighted pooling, single read of
// toks (128 MB). Self-normalizes its text row (no dependency on txtn array).
// grid = (NCHUNK, B) = 2048 blocks, block = 256 (8 warps x 4 rows).
// ---------------------------------------------------------------------------
__global__ void k_fused(const float* __restrict__ toks,
                        const float* __restrict__ txt,
                        const int* __restrict__ gt,
                        const float* __restrict__ p_log_attn_tau) {
    __shared__ float sm[8], sden[8];
    __shared__ float svec[8][Dq];

    int ch = blockIdx.x, b = blockIdx.y;
    int w = threadIdx.x >> 5, lane = threadIdx.x & 31;

    float at = expf(*p_log_attn_tau);
    at = fminf(fmaxf(at, 0.01f), 1.0f);
    float inv_at = 1.f / at;

    int g = __ldg(&gt[b]);
    const float4* xrow = (const float4*)(txt + (size_t)g * Dq);
    float4 xv[4];
    float ssx = 0.f;
#pragma unroll
    for (int i = 0; i < 4; i++) {
        xv[i] = xrow[lane + 32 * i];
        ssx += xv[i].x * xv[i].x + xv[i].y * xv[i].y + xv[i].z * xv[i].z + xv[i].w * xv[i].w;
    }
    ssx = warp_sum1(ssx);
    float scale_x = inv_at / fmaxf(sqrtf(ssx), 1e-12f);   // folds txt norm into s

    int row0 = b * Nq + ch * CH_ROWS + w * 4;
    const float4* base = (const float4*)(toks + (size_t)row0 * Dq);

    float m = -1e30f, den = 0.f;
    float4 acc[4];
#pragma unroll
    for (int i = 0; i < 4; i++) acc[i] = make_float4(0.f, 0.f, 0.f, 0.f);

    float4 t0[4], t1[4], u0[4], u1[4];
#pragma unroll
    for (int i = 0; i < 4; i++) t0[i] = __ldcs(&base[lane + 32 * i]);
#pragma unroll
    for (int i = 0; i < 4; i++) t1[i] = __ldcs(&base[128 + lane + 32 * i]);

#pragma unroll
    for (int rp = 0; rp < 2; rp++) {
        if (rp == 0) {
#pragma unroll
            for (int i = 0; i < 4; i++) u0[i] = __ldcs(&base[256 + lane + 32 * i]);
#pragma unroll
            for (int i = 0; i < 4; i++) u1[i] = __ldcs(&base[384 + lane + 32 * i]);
        }
        float ss0 = 0.f, dp0 = 0.f, ss1 = 0.f, dp1 = 0.f;
#pragma unroll
        for (int i = 0; i < 4; i++) {
            ss0 += t0[i].x * t0[i].x + t0[i].y * t0[i].y + t0[i].z * t0[i].z + t0[i].w * t0[i].w;
            dp0 += t0[i].x * xv[i].x + t0[i].y * xv[i].y + t0[i].z * xv[i].z + t0[i].w * xv[i].w;
            ss1 += t1[i].x * t1[i].x + t1[i].y * t1[i].y + t1[i].z * t1[i].z + t1[i].w * t1[i].w;
            dp1 += t1[i].x * xv[i].x + t1[i].y * xv[i].y + t1[i].z * xv[i].z + t1[i].w * xv[i].w;
        }
        warp_sum4(ss0, dp0, ss1, dp1);

        float rn0 = 1.f / fmaxf(sqrtf(ss0), 1e-12f);
        float rn1 = 1.f / fmaxf(sqrtf(ss1), 1e-12f);
        float s0 = dp0 * rn0 * scale_x;
        float s1 = dp1 * rn1 * scale_x;
        float mnew = fmaxf(m, fmaxf(s0, s1));
        float scale = expf(m - mnew);
        float e0 = expf(s0 - mnew);
        float e1 = expf(s1 - mnew);
        den = den * scale + e0 + e1;
        float c0 = e0 * rn0, c1 = e1 * rn1;
#pragma unroll
        for (int i = 0; i < 4; i++) {
            acc[i].x = fmaf(c1, t1[i].x, fmaf(c0, t0[i].x, acc[i].x * scale));
            acc[i].y = fmaf(c1, t1[i].y, fmaf(c0, t0[i].y, acc[i].y * scale));
            acc[i].z = fmaf(c1, t1[i].z, fmaf(c0, t0[i].z, acc[i].z * scale));
            acc[i].w = fmaf(c1, t1[i].w, fmaf(c0, t0[i].w, acc[i].w * scale));
        }
        m = mnew;
        if (rp == 0) {
#pragma unroll
            for (int i = 0; i < 4; i++) { t0[i] = u0[i]; t1[i] = u1[i]; }
        }
    }

    if (lane == 0) { sm[w] = m; sden[w] = den; }
    float4* sv = (float4*)svec[w];
#pragma unroll
    for (int i = 0; i < 4; i++) sv[lane + 32 * i] = acc[i];
    __syncthreads();

    float M = sm[0];
#pragma unroll
    for (int i = 1; i < 8; i++) M = fmaxf(M, sm[i]);
    float wsc[8];
    float denb = 0.f;
#pragma unroll
    for (int i = 0; i < 8; i++) { wsc[i] = expf(sm[i] - M); denb = fmaf(wsc[i], sden[i], denb); }

    int tid = threadIdx.x;
    float* outp = g_ppart + (size_t)(b * NCHUNK + ch) * Dq;
#pragma unroll
    for (int rep = 0; rep < 2; rep++) {
        int d = tid + rep * 256;
        float v = 0.f;
#pragma unroll
        for (int i = 0; i < 8; i++) v = fmaf(wsc[i], svec[i][d], v);
        outp[d] = v;
    }
    if (tid == 0) g_meta[b * NCHUNK + ch] = make_float2(M, denb);
}

// ---------------------------------------------------------------------------
// K3: combine NCHUNK partials per b -> pooled[b,:]. grid = B, block = 128.
// ---------------------------------------------------------------------------
__global__ void k_combine() {
    int b = blockIdx.x, tid = threadIdx.x;
    float2 mt[NCHUNK];
#pragma unroll
    for (int i = 0; i < NCHUNK; i++) mt[i] = g_meta[b * NCHUNK + i];
    float M = mt[0].x;
#pragma unroll
    for (int i = 1; i < NCHUNK; i++) M = fmaxf(M, mt[i].x);
    float den = 0.f;
    float sc[NCHUNK];
#pragma unroll
    for (int i = 0; i < NCHUNK; i++) { sc[i] = expf(mt[i].x - M); den = fmaf(sc[i], mt[i].y, den); }
    float inv_den = 1.f / den;

    const float4* part = (const float4*)(g_ppart + (size_t)b * NCHUNK * Dq);
    float4 acc = make_float4(0.f, 0.f, 0.f, 0.f);
#pragma unroll
    for (int i = 0; i < NCHUNK; i++) {
        float4 p = part[(size_t)i * (Dq / 4) + tid];
        acc.x = fmaf(sc[i], p.x, acc.x);
        acc.y = fmaf(sc[i], p.y, acc.y);
        acc.z = fmaf(sc[i], p.z, acc.z);
        acc.w = fmaf(sc[i], p.w, acc.w);
    }
    acc.x *= inv_den; acc.y *= inv_den; acc.z *= inv_den; acc.w *= inv_den;
    ((float4*)(g_pooled + (size_t)b * Dq))[tid] = acc;
}

// ---------------------------------------------------------------------------
// K4: partial logits via TF32 mma.sync (m16n8k8, fp32 accumulate).
// CTA = 256 thr = 8 warps (2 M x 4 N), tile 64 x 128, KCH = 64 in 2 sub-chunks
// of 32 with register prefetch (sub-chunk 1 loads fly under sub-chunk 0 MMAs).
// Text rows read RAW and scaled by g_txtrn during tf32 conversion.
// grid = (C/128, B/64, KSPLIT) = (8, 4, 8) = 256 CTAs.
// ---------------------------------------------------------------------------
__global__ void __launch_bounds__(256) k_gemm(const float* __restrict__ txt) {
    __shared__ __align__(16) uint32_t As[64][36];
    __shared__ __align__(16) uint32_t Bs[128][36];

    int tid = threadIdx.x;
    int c0 = blockIdx.x * 128;
    int b0 = blockIdx.y * 64;
    int kbase = blockIdx.z * KCH;

    int warp = tid >> 5, lane = tid & 31;
    int warpM = warp & 1;
    int warpN = warp >> 1;
    int qg = lane >> 2;
    int qt = lane & 3;

    int r = tid >> 3;          // 0..31
    int cc = (tid & 7) * 4;    // 0..28
    const float* pA = &g_pooled[(size_t)(b0 + r) * Dq + kbase + cc];
    const float* pB = &txt[(size_t)(c0 + r) * Dq + kbase + cc];
    float rnb0 = g_txtrn[c0 + r];
    float rnb1 = g_txtrn[c0 + r + 32];
    float rnb2 = g_txtrn[c0 + r + 64];
    float rnb3 = g_txtrn[c0 + r + 96];

    // stage-0 loads (k cols [kbase, kbase+32))
    float4 a0 = *(const float4*)pA;
    float4 a1 = *(const float4*)(pA + 32 * Dq);
    float4 v0 = *(const float4*)pB;
    float4 v1 = *(const float4*)(pB + 32 * Dq);
    float4 v2 = *(const float4*)(pB + 64 * Dq);
    float4 v3 = *(const float4*)(pB + 96 * Dq);

    float d[2][4][4];
#pragma unroll
    for (int mt = 0; mt < 2; mt++)
#pragma unroll
        for (int nt = 0; nt < 4; nt++)
#pragma unroll
            for (int f = 0; f < 4; f++) d[mt][nt][f] = 0.f;

#pragma unroll
    for (int stage = 0; stage < 2; stage++) {
        *(uint4*)&As[r][cc]      = tf32x4(a0);
        *(uint4*)&As[r + 32][cc] = tf32x4(a1);
        *(uint4*)&Bs[r][cc]      = tf32x4s(v0, rnb0);
        *(uint4*)&Bs[r + 32][cc] = tf32x4s(v1, rnb1);
        *(uint4*)&Bs[r + 64][cc] = tf32x4s(v2, rnb2);
        *(uint4*)&Bs[r + 96][cc] = tf32x4s(v3, rnb3);
        __syncthreads();

        if (stage == 0) {   // prefetch stage-1 (k cols [kbase+32, kbase+64))
            a0 = *(const float4*)(pA + 32);
            a1 = *(const float4*)(pA + 32 * Dq + 32);
            v0 = *(const float4*)(pB + 32);
            v1 = *(const float4*)(pB + 32 * Dq + 32);
            v2 = *(const float4*)(pB + 64 * Dq + 32);
            v3 = *(const float4*)(pB + 96 * Dq + 32);
        }

#pragma unroll
        for (int ks = 0; ks < 4; ks++) {
            int k = ks * 8;
            uint32_t a[2][4];
#pragma unroll
            for (int mt = 0; mt < 2; mt++) {
                int row = warpM * 32 + mt * 16 + qg;
                a[mt][0] = As[row][k + qt];
                a[mt][1] = As[row + 8][k + qt];
                a[mt][2] = As[row][k + qt + 4];
                a[mt][3] = As[row + 8][k + qt + 4];
            }
            uint32_t bf[4][2];
#pragma unroll
            for (int nt = 0; nt < 4; nt++) {
                int n = warpN * 32 + nt * 8 + qg;
                bf[nt][0] = Bs[n][k + qt];
                bf[nt][1] = Bs[n][k + qt + 4];
            }
#pragma unroll
            for (int mt = 0; mt < 2; mt++)
#pragma unroll
                for (int nt = 0; nt < 4; nt++) {
                    asm volatile(
                        "mma.sync.aligned.m16n8k8.row.col.f32.tf32.tf32.f32 "
                        "{%0,%1,%2,%3}, {%4,%5,%6,%7}, {%8,%9}, {%0,%1,%2,%3};"
                        : "+f"(d[mt][nt][0]), "+f"(d[mt][nt][1]),
                          "+f"(d[mt][nt][2]), "+f"(d[mt][nt][3])
                        : "r"(a[mt][0]), "r"(a[mt][1]), "r"(a[mt][2]), "r"(a[mt][3]),
                          "r"(bf[nt][0]), "r"(bf[nt][1]));
                }
        }
        __syncthreads();
    }

    float* dst = g_lpart + ((size_t)blockIdx.z * Bq) * Cq;
#pragma unroll
    for (int mt = 0; mt < 2; mt++) {
        int row0 = b0 + warpM * 32 + mt * 16 + qg;
#pragma unroll
        for (int nt = 0; nt < 4; nt++) {
            int col = c0 + warpN * 32 + nt * 8 + 2 * qt;
            *(float2*)&dst[(size_t)row0 * Cq + col] =
                make_float2(d[mt][nt][0], d[mt][nt][1]);
            *(float2*)&dst[(size_t)(row0 + 8) * Cq + col] =
                make_float2(d[mt][nt][2], d[mt][nt][3]);
        }
    }
}

// ---------------------------------------------------------------------------
// K5: cross entropy (summing KSPLIT logit partials) + mean via atomicAdd.
// grid = B, block = 256.
// ---------------------------------------------------------------------------
__global__ void k_ce(const float* __restrict__ p_log_tau,
                     const int* __restrict__ gt,
                     float* __restrict__ out) {
    __shared__ float red[256];
    int b = blockIdx.x, tid = threadIdx.x;
    float tau = expf(*p_log_tau);
    tau = fminf(fmaxf(tau, 0.01f), 1.0f);
    float inv = 1.f / tau;

    float l[4];
    float mx = -1e30f;
#pragma unroll
    for (int i = 0; i < 4; i++) {
        int idx = tid + i * 256;
        float v = 0.f;
#pragma unroll
        for (int ks = 0; ks < KSPLIT; ks++)
            v += g_lpart[((size_t)ks * Bq + b) * Cq + idx];
        l[i] = v * inv;
        mx = fmaxf(mx, l[i]);
    }
    red[tid] = mx;
    __syncthreads();
#pragma unroll
    for (int s = 128; s; s >>= 1) {
        if (tid < s) red[tid] = fmaxf(red[tid], red[tid + s]);
        __syncthreads();
    }
    mx = red[0];
    __syncthreads();

    float sum = 0.f;
#pragma unroll
    for (int i = 0; i < 4; i++) sum += expf(l[i] - mx);
    red[tid] = sum;
    __syncthreads();
#pragma unroll
    for (int s = 128; s; s >>= 1) {
        if (tid < s) red[tid] += red[tid + s];
        __syncthreads();
    }
    if (tid == 0) {
        int g = gt[b];
        float xg = 0.f;
#pragma unroll
        for (int ks = 0; ks < KSPLIT; ks++)
            xg += g_lpart[((size_t)ks * Bq + b) * Cq + g];
        xg *= inv;
        float nll = logf(red[0]) + mx - xg;
        atomicAdd(out, nll * (1.0f / (float)Bq));
    }
}

// ---------------------------------------------------------------------------
extern "C" void kernel_launch(void* const* d_in, const int* in_sizes, int n_in,
                              void* d_out, int out_size) {
    const float* toks         = (const float*)d_in[0];  // [B,N,D] f32
    const float* txt          = (const float*)d_in[1];  // [C,D]   f32
    const float* log_tau      = (const float*)d_in[2];  // scalar
    const float* log_attn_tau = (const float*)d_in[3];  // scalar
    const int*   gt           = (const int*)d_in[4];    // [B] int32
    float* out = (float*)d_out;

    k_txtnorm<<<Cq / 8, 256>>>(txt, out);
    dim3 gf(NCHUNK, Bq);
    k_fused<<<gf, 256>>>(toks, txt, gt, log_attn_tau);
    k_combine<<<Bq, 128>>>();
    dim3 gg(Cq / 128, Bq / 64, KSPLIT);
    k_gemm<<<gg, 256>>>(txt);
    k_ce<<<Bq, 256>>>(log_tau, gt, out);
}

// round 12
// speedup vs baseline: 1.0066x; 1.0066x over previous
#include <cuda_runtime.h>
#include <math.h>
#include <stdint.h>

#define Bq 256
#define Nq 256
#define Dq 512
#define Cq 1024
#define NCHUNK 8
#define CH_ROWS (Nq / NCHUNK)   // 32 rows per fused block
#define KSPLIT 8
#define KCH (Dq / KSPLIT)       // 64

// Scratch (device globals — no allocation allowed)
__device__ float  g_txtrn[Cq];                     // 1/||txt[c]||  (4 KB)
__device__ float  g_ppart[Bq * NCHUNK * Dq];       // partial weighted sums (4 MB)
__device__ float2 g_meta[Bq * NCHUNK];             // (m, den) per partial
__device__ float  g_pooled[Bq * Dq];               // pooled normalized tokens
__device__ float  g_lpart[KSPLIT * Bq * Cq];       // partial logits (8 MB)

__device__ __forceinline__ float warp_sum1(float v) {
#pragma unroll
    for (int o = 16; o; o >>= 1) v += __shfl_xor_sync(0xffffffffu, v, o);
    return v;
}

__device__ __forceinline__ void warp_sum4(float& a, float& b, float& c, float& d) {
#pragma unroll
    for (int o = 16; o; o >>= 1) {
        a += __shfl_xor_sync(0xffffffffu, a, o);
        b += __shfl_xor_sync(0xffffffffu, b, o);
        c += __shfl_xor_sync(0xffffffffu, c, o);
        d += __shfl_xor_sync(0xffffffffu, d, o);
    }
}

__device__ __forceinline__ uint32_t f2tf32(float v) {
    uint32_t r;
    asm("cvt.rna.tf32.f32 %0, %1;" : "=r"(r) : "f"(v));
    return r;
}
__device__ __forceinline__ uint4 tf32x4(float4 v) {
    return make_uint4(f2tf32(v.x), f2tf32(v.y), f2tf32(v.z), f2tf32(v.w));
}
__device__ __forceinline__ uint4 tf32x4s(float4 v, float s) {
    return make_uint4(f2tf32(v.x * s), f2tf32(v.y * s), f2tf32(v.z * s), f2tf32(v.w * s));
}

// ---------------------------------------------------------------------------
// K1: reciprocal norms of text rows. One warp per row. grid = 128, block = 256.
// ---------------------------------------------------------------------------
__global__ void k_txtnorm(const float* __restrict__ txt, float* __restrict__ out) {
    if (blockIdx.x == 0 && threadIdx.x == 0) out[0] = 0.f;
    int w = threadIdx.x >> 5, lane = threadIdx.x & 31;
    int row = blockIdx.x * 8 + w;
    const float4* src = (const float4*)(txt + (size_t)row * Dq);
    float ss = 0.f;
#pragma unroll
    for (int i = 0; i < 4; i++) {
        float4 v = src[lane + 32 * i];
        ss += v.x * v.x + v.y * v.y + v.z * v.z + v.w * v.w;
    }
    ss = warp_sum1(ss);
    if (lane == 0) g_txtrn[row] = 1.f / fmaxf(sqrtf(ss), 1e-12f);
}

// ---------------------------------------------------------------------------
// K2 (fused streaming pass): online softmax-weighted pooling, single read of
// toks (128 MB). Self-normalizes its text row.
// grid = (NCHUNK, B) = 2048 blocks, block = 256 (8 warps x 4 rows).
// ---------------------------------------------------------------------------
__global__ void k_fused(const float* __restrict__ toks,
                        const float* __restrict__ txt,
                        const int* __restrict__ gt,
                        const float* __restrict__ p_log_attn_tau) {
    __shared__ float sm[8], sden[8];
    __shared__ float svec[8][Dq];

    int ch = blockIdx.x, b = blockIdx.y;
    int w = threadIdx.x >> 5, lane = threadIdx.x & 31;

    float at = expf(*p_log_attn_tau);
    at = fminf(fmaxf(at, 0.01f), 1.0f);
    float inv_at = 1.f / at;

    int g = __ldg(&gt[b]);
    const float4* xrow = (const float4*)(txt + (size_t)g * Dq);
    float4 xv[4];
    float ssx = 0.f;
#pragma unroll
    for (int i = 0; i < 4; i++) {
        xv[i] = xrow[lane + 32 * i];
        ssx += xv[i].x * xv[i].x + xv[i].y * xv[i].y + xv[i].z * xv[i].z + xv[i].w * xv[i].w;
    }
    ssx = warp_sum1(ssx);
    float scale_x = inv_at / fmaxf(sqrtf(ssx), 1e-12f);

    int row0 = b * Nq + ch * CH_ROWS + w * 4;
    const float4* base = (const float4*)(toks + (size_t)row0 * Dq);

    float m = -1e30f, den = 0.f;
    float4 acc[4];
#pragma unroll
    for (int i = 0; i < 4; i++) acc[i] = make_float4(0.f, 0.f, 0.f, 0.f);

    float4 t0[4], t1[4], u0[4], u1[4];
#pragma unroll
    for (int i = 0; i < 4; i++) t0[i] = __ldcs(&base[lane + 32 * i]);
#pragma unroll
    for (int i = 0; i < 4; i++) t1[i] = __ldcs(&base[128 + lane + 32 * i]);

#pragma unroll
    for (int rp = 0; rp < 2; rp++) {
        if (rp == 0) {
#pragma unroll
            for (int i = 0; i < 4; i++) u0[i] = __ldcs(&base[256 + lane + 32 * i]);
#pragma unroll
            for (int i = 0; i < 4; i++) u1[i] = __ldcs(&base[384 + lane + 32 * i]);
        }
        float ss0 = 0.f, dp0 = 0.f, ss1 = 0.f, dp1 = 0.f;
#pragma unroll
        for (int i = 0; i < 4; i++) {
            ss0 += t0[i].x * t0[i].x + t0[i].y * t0[i].y + t0[i].z * t0[i].z + t0[i].w * t0[i].w;
            dp0 += t0[i].x * xv[i].x + t0[i].y * xv[i].y + t0[i].z * xv[i].z + t0[i].w * xv[i].w;
            ss1 += t1[i].x * t1[i].x + t1[i].y * t1[i].y + t1[i].z * t1[i].z + t1[i].w * t1[i].w;
            dp1 += t1[i].x * xv[i].x + t1[i].y * xv[i].y + t1[i].z * xv[i].z + t1[i].w * xv[i].w;
        }
        warp_sum4(ss0, dp0, ss1, dp1);

        float rn0 = 1.f / fmaxf(sqrtf(ss0), 1e-12f);
        float rn1 = 1.f / fmaxf(sqrtf(ss1), 1e-12f);
        float s0 = dp0 * rn0 * scale_x;
        float s1 = dp1 * rn1 * scale_x;
        float mnew = fmaxf(m, fmaxf(s0, s1));
        float scale = expf(m - mnew);
        float e0 = expf(s0 - mnew);
        float e1 = expf(s1 - mnew);
        den = den * scale + e0 + e1;
        float c0 = e0 * rn0, c1 = e1 * rn1;
#pragma unroll
        for (int i = 0; i < 4; i++) {
            acc[i].x = fmaf(c1, t1[i].x, fmaf(c0, t0[i].x, acc[i].x * scale));
            acc[i].y = fmaf(c1, t1[i].y, fmaf(c0, t0[i].y, acc[i].y * scale));
            acc[i].z = fmaf(c1, t1[i].z, fmaf(c0, t0[i].z, acc[i].z * scale));
            acc[i].w = fmaf(c1, t1[i].w, fmaf(c0, t0[i].w, acc[i].w * scale));
        }
        m = mnew;
        if (rp == 0) {
#pragma unroll
            for (int i = 0; i < 4; i++) { t0[i] = u0[i]; t1[i] = u1[i]; }
        }
    }

    if (lane == 0) { sm[w] = m; sden[w] = den; }
    float4* sv = (float4*)svec[w];
#pragma unroll
    for (int i = 0; i < 4; i++) sv[lane + 32 * i] = acc[i];
    __syncthreads();

    float M = sm[0];
#pragma unroll
    for (int i = 1; i < 8; i++) M = fmaxf(M, sm[i]);
    float wsc[8];
    float denb = 0.f;
#pragma unroll
    for (int i = 0; i < 8; i++) { wsc[i] = expf(sm[i] - M); denb = fmaf(wsc[i], sden[i], denb); }

    int tid = threadIdx.x;
    float* outp = g_ppart + (size_t)(b * NCHUNK + ch) * Dq;
#pragma unroll
    for (int rep = 0; rep < 2; rep++) {
        int d = tid + rep * 256;
        float v = 0.f;
#pragma unroll
        for (int i = 0; i < 8; i++) v = fmaf(wsc[i], svec[i][d], v);
        outp[d] = v;
    }
    if (tid == 0) g_meta[b * NCHUNK + ch] = make_float2(M, denb);
}

// ---------------------------------------------------------------------------
// K3: combine NCHUNK partials per b -> pooled[b,:]. grid = B, block = 128.
// ---------------------------------------------------------------------------
__global__ void k_combine() {
    int b = blockIdx.x, tid = threadIdx.x;
    float2 mt[NCHUNK];
#pragma unroll
    for (int i = 0; i < NCHUNK; i++) mt[i] = g_meta[b * NCHUNK + i];
    float M = mt[0].x;
#pragma unroll
    for (int i = 1; i < NCHUNK; i++) M = fmaxf(M, mt[i].x);
    float den = 0.f;
    float sc[NCHUNK];
#pragma unroll
    for (int i = 0; i < NCHUNK; i++) { sc[i] = expf(mt[i].x - M); den = fmaf(sc[i], mt[i].y, den); }
    float inv_den = 1.f / den;

    const float4* part = (const float4*)(g_ppart + (size_t)b * NCHUNK * Dq);
    float4 acc = make_float4(0.f, 0.f, 0.f, 0.f);
#pragma unroll
    for (int i = 0; i < NCHUNK; i++) {
        float4 p = part[(size_t)i * (Dq / 4) + tid];
        acc.x = fmaf(sc[i], p.x, acc.x);
        acc.y = fmaf(sc[i], p.y, acc.y);
        acc.z = fmaf(sc[i], p.z, acc.z);
        acc.w = fmaf(sc[i], p.w, acc.w);
    }
    acc.x *= inv_den; acc.y *= inv_den; acc.z *= inv_den; acc.w *= inv_den;
    ((float4*)(g_pooled + (size_t)b * Dq))[tid] = acc;
}

// ---------------------------------------------------------------------------
// K4: partial logits via TF32 mma.sync (m16n8k8, fp32 accumulate).
// Tile 32b x 64c, block = 128 (4 warps: 2 M x 2 N, each m16n32), KCH = 64 in
// 2 sub-chunks of 32 with register prefetch.
// grid = (C/64, B/32, KSPLIT) = (16, 8, 8) = 1024 CTAs (~7/SM, one wave).
// ---------------------------------------------------------------------------
__global__ void __launch_bounds__(128) k_gemm(const float* __restrict__ txt) {
    __shared__ __align__(16) uint32_t As[32][36];
    __shared__ __align__(16) uint32_t Bs[64][36];

    int tid = threadIdx.x;
    int c0 = blockIdx.x * 64;
    int b0 = blockIdx.y * 32;
    int kbase = blockIdx.z * KCH;

    int warp = tid >> 5, lane = tid & 31;
    int warpM = warp & 1;          // 2 m-tiles of 16
    int warpN = warp >> 1;         // 2 n-groups of 32
    int qg = lane >> 2;
    int qt = lane & 3;

    int r = tid >> 3;          // 0..15
    int cc = (tid & 7) * 4;    // 0..28
    const float* pA = &g_pooled[(size_t)(b0 + r) * Dq + kbase + cc];
    const float* pB = &txt[(size_t)(c0 + r) * Dq + kbase + cc];
    float rnb0 = g_txtrn[c0 + r];
    float rnb1 = g_txtrn[c0 + r + 16];
    float rnb2 = g_txtrn[c0 + r + 32];
    float rnb3 = g_txtrn[c0 + r + 48];

    // stage-0 loads (k cols [kbase, kbase+32))
    float4 a0 = *(const float4*)pA;
    float4 a1 = *(const float4*)(pA + 16 * Dq);
    float4 v0 = *(const float4*)pB;
    float4 v1 = *(const float4*)(pB + 16 * Dq);
    float4 v2 = *(const float4*)(pB + 32 * Dq);
    float4 v3 = *(const float4*)(pB + 48 * Dq);

    float d[4][4];   // [ntile][frag]
#pragma unroll
    for (int nt = 0; nt < 4; nt++)
#pragma unroll
        for (int f = 0; f < 4; f++) d[nt][f] = 0.f;

#pragma unroll
    for (int stage = 0; stage < 2; stage++) {
        *(uint4*)&As[r][cc]      = tf32x4(a0);
        *(uint4*)&As[r + 16][cc] = tf32x4(a1);
        *(uint4*)&Bs[r][cc]      = tf32x4s(v0, rnb0);
        *(uint4*)&Bs[r + 16][cc] = tf32x4s(v1, rnb1);
        *(uint4*)&Bs[r + 32][cc] = tf32x4s(v2, rnb2);
        *(uint4*)&Bs[r + 48][cc] = tf32x4s(v3, rnb3);
        __syncthreads();

        if (stage == 0) {   // prefetch stage-1 (k cols [kbase+32, kbase+64))
            a0 = *(const float4*)(pA + 32);
            a1 = *(const float4*)(pA + 16 * Dq + 32);
            v0 = *(const float4*)(pB + 32);
            v1 = *(const float4*)(pB + 16 * Dq + 32);
            v2 = *(const float4*)(pB + 32 * Dq + 32);
            v3 = *(const float4*)(pB + 48 * Dq + 32);
        }

#pragma unroll
        for (int ks = 0; ks < 4; ks++) {
            int k = ks * 8;
            int row = warpM * 16 + qg;
            uint32_t af0 = As[row][k + qt];
            uint32_t af1 = As[row + 8][k + qt];
            uint32_t af2 = As[row][k + qt + 4];
            uint32_t af3 = As[row + 8][k + qt + 4];
#pragma unroll
            for (int nt = 0; nt < 4; nt++) {
                int n = warpN * 32 + nt * 8 + qg;
                uint32_t bf0 = Bs[n][k + qt];
                uint32_t bf1 = Bs[n][k + qt + 4];
                asm volatile(
                    "mma.sync.aligned.m16n8k8.row.col.f32.tf32.tf32.f32 "
                    "{%0,%1,%2,%3}, {%4,%5,%6,%7}, {%8,%9}, {%0,%1,%2,%3};"
                    : "+f"(d[nt][0]), "+f"(d[nt][1]), "+f"(d[nt][2]), "+f"(d[nt][3])
                    : "r"(af0), "r"(af1), "r"(af2), "r"(af3), "r"(bf0), "r"(bf1));
            }
        }
        __syncthreads();
    }

    float* dst = g_lpart + ((size_t)blockIdx.z * Bq) * Cq;
    int row0 = b0 + warpM * 16 + qg;
#pragma unroll
    for (int nt = 0; nt < 4; nt++) {
        int col = c0 + warpN * 32 + nt * 8 + 2 * qt;
        *(float2*)&dst[(size_t)row0 * Cq + col]       = make_float2(d[nt][0], d[nt][1]);
        *(float2*)&dst[(size_t)(row0 + 8) * Cq + col] = make_float2(d[nt][2], d[nt][3]);
    }
}

// ---------------------------------------------------------------------------
// K5: cross entropy (summing KSPLIT logit partials) + mean via atomicAdd.
// grid = B, block = 256.
// ---------------------------------------------------------------------------
__global__ void k_ce(const float* __restrict__ p_log_tau,
                     const int* __restrict__ gt,
                     float* __restrict__ out) {
    __shared__ float red[256];
    int b = blockIdx.x, tid = threadIdx.x;
    float tau = expf(*p_log_tau);
    tau = fminf(fmaxf(tau, 0.01f), 1.0f);
    float inv = 1.f / tau;

    float l[4];
    float mx = -1e30f;
#pragma unroll
    for (int i = 0; i < 4; i++) {
        int idx = tid + i * 256;
        float v = 0.f;
#pragma unroll
        for (int ks = 0; ks < KSPLIT; ks++)
            v += g_lpart[((size_t)ks * Bq + b) * Cq + idx];
        l[i] = v * inv;
        mx = fmaxf(mx, l[i]);
    }
    red[tid] = mx;
    __syncthreads();
#pragma unroll
    for (int s = 128; s; s >>= 1) {
        if (tid < s) red[tid] = fmaxf(red[tid], red[tid + s]);
        __syncthreads();
    }
    mx = red[0];
    __syncthreads();

    float sum = 0.f;
#pragma unroll
    for (int i = 0; i < 4; i++) sum += expf(l[i] - mx);
    red[tid] = sum;
    __syncthreads();
#pragma unroll
    for (int s = 128; s; s >>= 1) {
        if (tid < s) red[tid] += red[tid + s];
        __syncthreads();
    }
    if (tid == 0) {
        int g = gt[b];
        float xg = 0.f;
#pragma unroll
        for (int ks = 0; ks < KSPLIT; ks++)
            xg += g_lpart[((size_t)ks * Bq + b) * Cq + g];
        xg *= inv;
        float nll = logf(red[0]) + mx - xg;
        atomicAdd(out, nll * (1.0f / (float)Bq));
    }
}

// ---------------------------------------------------------------------------
extern "C" void kernel_launch(void* const* d_in, const int* in_sizes, int n_in,
                              void* d_out, int out_size) {
    const float* toks         = (const float*)d_in[0];  // [B,N,D] f32
    const float* txt          = (const float*)d_in[1];  // [C,D]   f32
    const float* log_tau      = (const float*)d_in[2];  // scalar
    const float* log_attn_tau = (const float*)d_in[3];  // scalar
    const int*   gt           = (const int*)d_in[4];    // [B] int32
    float* out = (float*)d_out;

    k_txtnorm<<<Cq / 8, 256>>>(txt, out);
    dim3 gf(NCHUNK, Bq);
    k_fused<<<gf, 256>>>(toks, txt, gt, log_attn_tau);
    k_combine<<<Bq, 128>>>();
    dim3 gg(Cq / 64, Bq / 32, KSPLIT);
    k_gemm<<<gg, 128>>>(txt);
    k_ce<<<Bq, 256>>>(log_tau, gt, out);
}